// round 1
// baseline (speedup 1.0000x reference)
#include <cuda_runtime.h>
#include <math.h>

#define Bn 16384
#define Dn 512
#define Kn 2048

// ---------------- workspaces (device globals; no runtime allocation) ----------------
__device__ float g_L1[33554432];   // [B,K] logits view 1
__device__ float g_L2[33554432];   // [B,K] logits view 2
__device__ float g_zn1[8388608];   // [B,D] normalized z1
__device__ float g_zn2[8388608];
__device__ float g_G1[262144];     // [D,D] z^T z
__device__ float g_G2[262144];
__device__ float g_csum[2][512];
__device__ float g_csq[2][512];
__device__ float g_t[2048];        // sinkhorn column-sum scratch
__device__ float g_u1[2048], g_u2[2048], g_lu1[2048], g_lu2[2048];
__device__ float g_v1[16384], g_v2[16384];
__device__ float g_lse1[16384], g_lse2[16384];
__device__ int   g_am1[16384], g_am2[16384];
__device__ double g_S[2];
__device__ double g_ce[2];
__device__ float g_avgp[2048];
__device__ int   g_hist[2048];
__device__ int   g_accc[2];
__device__ float g_misc[4];        // var1, cov1, var2, cov2

__device__ __forceinline__ float* LB(int v){ return v ? g_L2 : g_L1; }
__device__ __forceinline__ float* ZN(int v){ return v ? g_zn2 : g_zn1; }
__device__ __forceinline__ float* UB(int v){ return v ? g_u2 : g_u1; }
__device__ __forceinline__ float* VBv(int v){ return v ? g_v2 : g_v1; }
__device__ __forceinline__ float* LUB(int v){ return v ? g_lu2 : g_lu1; }
__device__ __forceinline__ float* LSEB(int v){ return v ? g_lse2 : g_lse1; }
__device__ __forceinline__ int*   AMB(int v){ return v ? g_am2 : g_am1; }
__device__ __forceinline__ float* GBv(int v){ return v ? g_G2 : g_G1; }

// ---------------- zeroing ----------------
__global__ void k_zero_main(){
    int i = blockIdx.x*256 + threadIdx.x;
    if (i < 2048){ g_avgp[i]=0.f; g_hist[i]=0; }
    if (i < 512){ g_csum[0][i]=0.f; g_csum[1][i]=0.f; g_csq[0][i]=0.f; g_csq[1][i]=0.f; }
    if (i == 0){
        g_S[0]=0.0; g_S[1]=0.0; g_ce[0]=0.0; g_ce[1]=0.0;
        g_accc[0]=0; g_accc[1]=0;
        g_misc[0]=0.f; g_misc[1]=0.f; g_misc[2]=0.f; g_misc[3]=0.f;
    }
}
__global__ void k_zero_G(){
    int i = blockIdx.x*256 + threadIdx.x;
    if (i < 262144){ g_G1[i]=0.f; g_G2[i]=0.f; }
}
__global__ void k_zero_t(){
    int i = blockIdx.x*256 + threadIdx.x;
    if (i < 2048) g_t[i]=0.f;
}

// ---------------- column mean / sumsq (for var + cov correction) ----------------
__global__ void k_colstats(const float* __restrict__ z, int view){
    int d = threadIdx.x;                     // 512
    size_t r0 = (size_t)blockIdx.x * 128;    // 128 blocks
    float s=0.f, q=0.f;
    #pragma unroll 4
    for (int r=0;r<128;r++){ float v = z[(r0+r)*512 + d]; s += v; q += v*v; }
    atomicAdd(&g_csum[view][d], s);
    atomicAdd(&g_csq[view][d], q);
}

// ---------------- row l2 normalize ----------------
__global__ void k_rownorm(const float* __restrict__ z, int view){
    int row = blockIdx.x, t = threadIdx.x;   // 128 threads, D=512 -> 1 float4/thread
    __shared__ float sm[128];
    float4 v = reinterpret_cast<const float4*>(z)[(size_t)row*128 + t];
    float s = v.x*v.x + v.y*v.y + v.z*v.z + v.w*v.w;
    sm[t]=s; __syncthreads();
    for (int o=64;o;o>>=1){ if (t<o) sm[t]+=sm[t+o]; __syncthreads(); }
    float inv = 1.f / fmaxf(sqrtf(sm[0]), 1e-12f);
    float* zn = ZN(view);
    reinterpret_cast<float4*>(zn)[(size_t)row*128 + t] =
        make_float4(v.x*inv, v.y*inv, v.z*inv, v.w*inv);
}

// ---------------- G = z^T z  (split-K over batch, atomic epilogue) ----------------
__global__ void k_covgemm(const float* __restrict__ z, int view){
    __shared__ __align__(16) float As[16][128];
    __shared__ __align__(16) float Bs[16][128];
    int i0 = blockIdx.y*128, j0 = blockIdx.x*128;
    size_t b0 = (size_t)blockIdx.z * 512;
    int tid = threadIdx.x;
    int tx = tid & 15, ty = tid >> 4;
    float acc[8][8];
    #pragma unroll
    for (int u=0;u<8;u++)
        #pragma unroll
        for (int v=0;v<8;v++) acc[u][v]=0.f;
    for (int kb=0; kb<512; kb+=16){
        #pragma unroll
        for (int l=0;l<2;l++){
            int idx = tid + l*256;            // 0..511
            int row = idx >> 5;               // 16 rows
            int c4  = idx & 31;               // 32 float4 per row
            const float* base = z + (b0 + kb + row)*512;
            *reinterpret_cast<float4*>(&As[row][c4*4]) =
                *reinterpret_cast<const float4*>(base + i0 + c4*4);
            *reinterpret_cast<float4*>(&Bs[row][c4*4]) =
                *reinterpret_cast<const float4*>(base + j0 + c4*4);
        }
        __syncthreads();
        #pragma unroll
        for (int kk=0;kk<16;kk++){
            float a[8], b[8];
            *(float4*)a     = *(float4*)&As[kk][ty*8];
            *(float4*)(a+4) = *(float4*)&As[kk][ty*8+4];
            *(float4*)b     = *(float4*)&Bs[kk][tx*8];
            *(float4*)(b+4) = *(float4*)&Bs[kk][tx*8+4];
            #pragma unroll
            for (int u=0;u<8;u++)
                #pragma unroll
                for (int v=0;v<8;v++) acc[u][v] = fmaf(a[u], b[v], acc[u][v]);
        }
        __syncthreads();
    }
    float* G = GBv(view);
    #pragma unroll
    for (int u=0;u<8;u++)
        #pragma unroll
        for (int v=0;v<8;v++)
            atomicAdd(&G[(size_t)(i0+ty*8+u)*512 + j0+tx*8+v], acc[u][v]);
}

// ---------------- covariance / variance losses ----------------
__global__ void k_covfin(int view){
    int i = blockIdx.x, j = threadIdx.x;    // 512 x 512
    __shared__ float sm[512];
    const float* G = GBv(view);
    float mi = g_csum[view][i] * (1.f/16384.f);
    float mj = g_csum[view][j] * (1.f/16384.f);
    float Cij = (G[(size_t)i*512 + j] - 16384.f*mi*mj) * (1.f/16383.f);
    float c2 = (i==j) ? 0.f : Cij*Cij;
    sm[j]=c2; __syncthreads();
    for (int o=256;o;o>>=1){ if (j<o) sm[j]+=sm[j+o]; __syncthreads(); }
    if (j==0) atomicAdd(&g_misc[view*2+1], sm[0]*(1.f/512.f));
    if (j==i){
        float var = Cij;
        float term = fmaxf(0.f, 0.2f - sqrtf(var + 1e-8f));
        atomicAdd(&g_misc[view*2+0], term*(1.f/512.f));
    }
}

// ---------------- logits SGEMM: C[B,K] = zn @ W^T ----------------
__global__ void __launch_bounds__(256,2) k_sgemm(int view, const float* __restrict__ W){
    __shared__ __align__(16) float As[16][128];
    __shared__ __align__(16) float Bs[16][128];
    const float* A = ZN(view);
    float* C = LB(view);
    int bm = blockIdx.y*128, bn = blockIdx.x*128;
    int tid = threadIdx.x, tx = tid & 15, ty = tid >> 4;
    float acc[8][8];
    #pragma unroll
    for (int u=0;u<8;u++)
        #pragma unroll
        for (int v=0;v<8;v++) acc[u][v]=0.f;
    for (int k0=0;k0<512;k0+=16){
        #pragma unroll
        for (int l=0;l<2;l++){
            int idx = tid + l*256;            // 0..511
            int row = idx >> 2;               // 128 rows
            int kq  = idx & 3;                // 4 float4 = 16 k
            float4 a = *reinterpret_cast<const float4*>(A + (size_t)(bm+row)*512 + k0 + kq*4);
            As[kq*4+0][row]=a.x; As[kq*4+1][row]=a.y; As[kq*4+2][row]=a.z; As[kq*4+3][row]=a.w;
            float4 b = *reinterpret_cast<const float4*>(W + (size_t)(bn+row)*512 + k0 + kq*4);
            Bs[kq*4+0][row]=b.x; Bs[kq*4+1][row]=b.y; Bs[kq*4+2][row]=b.z; Bs[kq*4+3][row]=b.w;
        }
        __syncthreads();
        #pragma unroll
        for (int kk=0;kk<16;kk++){
            float a[8], b[8];
            *(float4*)a     = *(float4*)&As[kk][ty*8];
            *(float4*)(a+4) = *(float4*)&As[kk][ty*8+4];
            *(float4*)b     = *(float4*)&Bs[kk][tx*8];
            *(float4*)(b+4) = *(float4*)&Bs[kk][tx*8+4];
            #pragma unroll
            for (int u=0;u<8;u++)
                #pragma unroll
                for (int v=0;v<8;v++) acc[u][v] = fmaf(a[u], b[v], acc[u][v]);
        }
        __syncthreads();
    }
    #pragma unroll
    for (int u=0;u<8;u++)
        #pragma unroll
        for (int v=0;v<8;v+=4)
            *reinterpret_cast<float4*>(C + (size_t)(bm+ty*8+u)*2048 + bn+tx*8+v) =
                make_float4(acc[u][v],acc[u][v+1],acc[u][v+2],acc[u][v+3]);
}

// ---------------- per-row max/argmax + logsumexp of L/TEMP ----------------
__global__ void k_rowstats(int view){
    int b = blockIdx.x, tid = threadIdx.x;  // 256 threads x 8 elems
    const float* L = LB(view);
    const float4* Lr = reinterpret_cast<const float4*>(L + (size_t)b*2048);
    float4 x0 = Lr[tid*2], x1 = Lr[tid*2+1];
    float v[8] = {x0.x,x0.y,x0.z,x0.w,x1.x,x1.y,x1.z,x1.w};
    float m = v[0]; int mi = tid*8;
    #pragma unroll
    for (int j=1;j<8;j++) if (v[j]>m){ m=v[j]; mi=tid*8+j; }
    __shared__ float sm[256]; __shared__ int si[256];
    sm[tid]=m; si[tid]=mi; __syncthreads();
    for (int o=128;o;o>>=1){
        if (tid<o){
            if (sm[tid+o]>sm[tid] || (sm[tid+o]==sm[tid] && si[tid+o]<si[tid])){
                sm[tid]=sm[tid+o]; si[tid]=si[tid+o];
            }
        }
        __syncthreads();
    }
    float M = sm[0]; int gidx = si[0];
    __syncthreads();
    float se=0.f;
    #pragma unroll
    for (int j=0;j<8;j++) se += __expf((v[j]-M)*10.f);
    sm[tid]=se; __syncthreads();
    for (int o=128;o;o>>=1){ if (tid<o) sm[tid]+=sm[tid+o]; __syncthreads(); }
    if (tid==0){ LSEB(view)[b] = M*10.f + logf(sm[0]); AMB(view)[b] = gidx; }
}

// ---------------- sinkhorn: weighted column sums t[k] = sum_b exp(20 L) * w[b] ----------------
__global__ void k_colpass(int view, int useV, int withS){
    __shared__ float sm[256];
    int k = blockIdx.x*256 + threadIdx.x;   // grid.x = 8
    size_t b0 = (size_t)blockIdx.y * 128;   // grid.y = 128
    const float* L = LB(view);
    float s = 0.f;
    if (useV){
        const float* v = VBv(view);
        #pragma unroll 8
        for (int r=0;r<128;r++)
            s += __expf(20.f * L[(b0+r)*2048 + k]) * v[b0+r];
    } else {
        #pragma unroll 8
        for (int r=0;r<128;r++)
            s += __expf(20.f * L[(b0+r)*2048 + k]);
    }
    atomicAdd(&g_t[k], s);
    if (withS){
        sm[threadIdx.x]=s; __syncthreads();
        for (int o=128;o;o>>=1){ if (threadIdx.x<o) sm[threadIdx.x]+=sm[threadIdx.x+o]; __syncthreads(); }
        if (threadIdx.x==0) atomicAdd(&g_S[view], (double)sm[0]);
    }
}

__global__ void k_uinit(int view){
    int k = blockIdx.x*256 + threadIdx.x;
    UB(view)[k] = (float)(g_S[view]) / (2048.f * g_t[k]);
}
__global__ void k_ufromt(int view){
    int k = blockIdx.x*256 + threadIdx.x;
    UB(view)[k] = 1.f / (2048.f * g_t[k]);
}
__global__ void k_logu(int view){
    int k = blockIdx.x*256 + threadIdx.x;
    LUB(view)[k] = logf(UB(view)[k]);
}

// ---------------- sinkhorn: v[b] = 1/(B * sum_k exp(20 L) u[k]) ----------------
__global__ void k_rowpass(int view){
    int b = blockIdx.x, tid = threadIdx.x;  // 256
    const float* L = LB(view);
    const float4* Lr = reinterpret_cast<const float4*>(L + (size_t)b*2048);
    const float4* Ur = reinterpret_cast<const float4*>(UB(view));
    float s = 0.f;
    #pragma unroll
    for (int j=0;j<2;j++){
        float4 x = Lr[tid*2+j]; float4 uu = Ur[tid*2+j];
        s += __expf(20.f*x.x)*uu.x + __expf(20.f*x.y)*uu.y
           + __expf(20.f*x.z)*uu.z + __expf(20.f*x.w)*uu.w;
    }
    __shared__ float sm[256];
    sm[tid]=s; __syncthreads();
    for (int o=128;o;o>>=1){ if (tid<o) sm[tid]+=sm[tid+o]; __syncthreads(); }
    if (tid==0) VBv(view)[b] = 1.f / (16384.f * sm[0]);
}

// ---------------- fused final pass: CE, avg_probs, acc ----------------
__global__ void k_final(){
    __shared__ float s_avgp[2048];
    __shared__ float smf[256]; __shared__ int smi[256];
    __shared__ double smd[256];
    int tid = threadIdx.x;
    int kbase = tid*8;
    float U1[8],U2[8],LU1[8],LU2[8];
    #pragma unroll
    for (int j=0;j<8;j++){
        U1[j]=g_u1[kbase+j]; U2[j]=g_u2[kbase+j];
        LU1[j]=g_lu1[kbase+j]; LU2[j]=g_lu2[kbase+j];
        s_avgp[kbase+j]=0.f;
    }
    __syncthreads();
    double tce1=0.0, tce2=0.0;
    int tacc1=0, tacc2=0;
    int b0 = blockIdx.x*16;
    for (int r=0;r<16;r++){
        int b = b0 + r;
        const float4* L1r = reinterpret_cast<const float4*>(g_L1 + (size_t)b*2048);
        const float4* L2r = reinterpret_cast<const float4*>(g_L2 + (size_t)b*2048);
        float4 a0=L1r[tid*2], a1=L1r[tid*2+1];
        float4 c0=L2r[tid*2], c1=L2r[tid*2+1];
        float A[8]={a0.x,a0.y,a0.z,a0.w,a1.x,a1.y,a1.z,a1.w};
        float C[8]={c0.x,c0.y,c0.z,c0.w,c1.x,c1.y,c1.z,c1.w};
        float cv1 = 16384.f*g_v1[b], cv2 = 16384.f*g_v2[b];
        float ls1 = g_lse1[b], ls2 = g_lse2[b];
        float sc1=0.f, sc2=0.f;
        float m1=-1e30f, m2=-1e30f; int i1=0, i2=0;
        #pragma unroll
        for (int j=0;j<8;j++){
            float a=A[j], c=C[j];
            float lp1 = 10.f*a - ls1;
            float lp2 = 10.f*c - ls2;
            float t1 = cv1*U1[j]*__expf(20.f*a);
            float t2 = cv2*U2[j]*__expf(20.f*c);
            sc1 += t1*lp2;
            sc2 += t2*lp1;
            s_avgp[kbase+j] += __expf(lp1) + __expf(lp2);
            float g1 = 20.f*a + LU1[j];
            if (g1>m1){ m1=g1; i1=kbase+j; }
            float g2 = 20.f*c + LU2[j];
            if (g2>m2){ m2=g2; i2=kbase+j; }
        }
        tce1 += (double)sc1; tce2 += (double)sc2;
        // argmax(tgt_probs_2) vs argmax(l1)
        smf[tid]=m2; smi[tid]=i2; __syncthreads();
        for (int o=128;o;o>>=1){
            if (tid<o && (smf[tid+o]>smf[tid] || (smf[tid+o]==smf[tid] && smi[tid+o]<smi[tid]))){
                smf[tid]=smf[tid+o]; smi[tid]=smi[tid+o];
            }
            __syncthreads();
        }
        if (tid==0 && smi[0]==g_am1[b]) tacc1++;
        __syncthreads();
        // argmax(tgt_probs_1) vs argmax(l2)
        smf[tid]=m1; smi[tid]=i1; __syncthreads();
        for (int o=128;o;o>>=1){
            if (tid<o && (smf[tid+o]>smf[tid] || (smf[tid+o]==smf[tid] && smi[tid+o]<smi[tid]))){
                smf[tid]=smf[tid+o]; smi[tid]=smi[tid+o];
            }
            __syncthreads();
        }
        if (tid==0 && smi[0]==g_am2[b]) tacc2++;
        __syncthreads();
    }
    smd[tid]=tce1; __syncthreads();
    for (int o=128;o;o>>=1){ if (tid<o) smd[tid]+=smd[tid+o]; __syncthreads(); }
    if (tid==0) atomicAdd(&g_ce[0], smd[0]);
    __syncthreads();
    smd[tid]=tce2; __syncthreads();
    for (int o=128;o;o>>=1){ if (tid<o) smd[tid]+=smd[tid+o]; __syncthreads(); }
    if (tid==0) atomicAdd(&g_ce[1], smd[0]);
    __syncthreads();
    #pragma unroll
    for (int j=0;j<8;j++) atomicAdd(&g_avgp[kbase+j], s_avgp[kbase+j]);
    if (tid==0){ atomicAdd(&g_accc[0], tacc1); atomicAdd(&g_accc[1], tacc2); }
}

// ---------------- histogram of argmaxes ----------------
__global__ void k_hist(){
    int i = blockIdx.x*256 + threadIdx.x;
    if (i < 16384){
        atomicAdd(&g_hist[g_am1[i]], 1);
        atomicAdd(&g_hist[g_am2[i]], 1);
    }
}

// ---------------- assemble 7 outputs ----------------
__global__ void k_finalize(float* __restrict__ out){
    __shared__ double smd[256];
    int tid = threadIdx.x;
    double sh=0.0, sp=0.0;
    for (int j=0;j<8;j++){
        int k = tid*8 + j;
        double hp = (double)g_hist[k] / 32768.0;
        sh += hp * log(hp + 1e-7);
        double pp = (double)g_avgp[k] / 32768.0;
        sp += pp * log(pp + 1e-7);
    }
    smd[tid]=sh; __syncthreads();
    for (int o=128;o;o>>=1){ if (tid<o) smd[tid]+=smd[tid+o]; __syncthreads(); }
    double H = smd[0]; __syncthreads();
    smd[tid]=sp; __syncthreads();
    for (int o=128;o;o>>=1){ if (tid<o) smd[tid]+=smd[tid+o]; __syncthreads(); }
    double P = smd[0];
    if (tid==0){
        double ce = -0.5 * (g_ce[0]/16384.0 + g_ce[1]/16384.0);
        float lvar = g_misc[0] + g_misc[2];
        float lcov = g_misc[1] + g_misc[3];
        double loss = 15.0*ce + (double)lvar + (double)lcov;
        out[0] = (float)loss;
        out[1] = (float)ce;
        out[2] = lvar;
        out[3] = lcov;
        out[4] = (float)exp(-H);
        out[5] = (float)exp(-P);
        out[6] = 0.5f * ((float)g_accc[0] + (float)g_accc[1]) / 16384.f;
    }
}

// ---------------- launch ----------------
extern "C" void kernel_launch(void* const* d_in, const int* in_sizes, int n_in,
                              void* d_out, int out_size){
    const float* z1 = (const float*)d_in[0];
    const float* z2 = (const float*)d_in[1];
    const float* W  = (const float*)d_in[2];
    float* out = (float*)d_out;

    k_zero_main<<<8,256>>>();
    k_zero_G<<<1024,256>>>();

    for (int view=0; view<2; view++){
        const float* z = view ? z2 : z1;
        k_colstats<<<128,512>>>(z, view);
        k_rownorm<<<Bn,128>>>(z, view);
        k_covgemm<<<dim3(4,4,32),256>>>(z, view);
    }
    k_covfin<<<512,512>>>(0);
    k_covfin<<<512,512>>>(1);

    for (int view=0; view<2; view++){
        k_sgemm<<<dim3(16,128),256>>>(view, W);
        k_rowstats<<<Bn,256>>>(view);
    }

    for (int view=0; view<2; view++){
        // iter 1
        k_zero_t<<<8,256>>>();
        k_colpass<<<dim3(8,128),256>>>(view, 0, 1);   // colsumE + S
        k_uinit<<<8,256>>>(view);
        k_rowpass<<<Bn,256>>>(view);
        // iter 2
        k_zero_t<<<8,256>>>();
        k_colpass<<<dim3(8,128),256>>>(view, 1, 0);
        k_ufromt<<<8,256>>>(view);
        k_rowpass<<<Bn,256>>>(view);
        // iter 3
        k_zero_t<<<8,256>>>();
        k_colpass<<<dim3(8,128),256>>>(view, 1, 0);
        k_ufromt<<<8,256>>>(view);
        k_logu<<<8,256>>>(view);
        k_rowpass<<<Bn,256>>>(view);
    }

    k_final<<<1024,256>>>();
    k_hist<<<64,256>>>();
    k_finalize<<<1,256>>>(out);
}

// round 3
// speedup vs baseline: 1.6642x; 1.6642x over previous
#include <cuda_runtime.h>
#include <cuda_bf16.h>
#include <math.h>
#include <stdint.h>

#define Bn 16384
#define Dn 512
#define Kn 2048

// ======================= PTX helpers (baseline compute_103-safe) =======================
__device__ __forceinline__ uint32_t smem_to_u32(const void* p){
    uint32_t a;
    asm("{ .reg .u64 t; cvta.to.shared.u64 t, %1; cvt.u32.u64 %0, t; }" : "=r"(a) : "l"(p));
    return a;
}
#define CP_ASYNC16(dst, src) \
    asm volatile("cp.async.cg.shared.global [%0], [%1], 16;" :: "r"(dst), "l"(src) : "memory")
#define CP_COMMIT() asm volatile("cp.async.commit_group;" ::: "memory")
#define CP_WAIT(n)  asm volatile("cp.async.wait_group %0;" :: "n"(n) : "memory")
#define LDMATRIX_X4(r0,r1,r2,r3,addr) \
    asm volatile("ldmatrix.sync.aligned.m8n8.x4.shared.b16 {%0,%1,%2,%3}, [%4];" \
        : "=r"(r0),"=r"(r1),"=r"(r2),"=r"(r3) : "r"(addr))

__device__ __forceinline__ void mma16816(float* c, const uint32_t* a, const uint32_t* b){
    asm volatile("mma.sync.aligned.m16n8k16.row.col.f32.bf16.bf16.f32 "
        "{%0,%1,%2,%3}, {%4,%5,%6,%7}, {%8,%9}, {%0,%1,%2,%3};"
        : "+f"(c[0]),"+f"(c[1]),"+f"(c[2]),"+f"(c[3])
        : "r"(a[0]),"r"(a[1]),"r"(a[2]),"r"(a[3]), "r"(b[0]),"r"(b[1]));
}

// ======================= workspaces =======================
__device__ float g_L1[33554432];   // [B,K] logits view 1
__device__ float g_L2[33554432];
__device__ __nv_bfloat16 g_znh1[8388608], g_znl1[8388608];   // zn hi/lo [B,D]
__device__ __nv_bfloat16 g_znh2[8388608], g_znl2[8388608];
__device__ __nv_bfloat16 g_zth1[8388608], g_ztl1[8388608];   // z^T hi/lo [D,B]
__device__ __nv_bfloat16 g_zth2[8388608], g_ztl2[8388608];
__device__ __nv_bfloat16 g_wh[1048576], g_wl[1048576];       // W hi/lo [K,D]
__device__ float g_G1[262144], g_G2[262144];
__device__ float g_csum[2][512];
__device__ float g_t[2048];
__device__ float g_u1[2048], g_u2[2048], g_lu1[2048], g_lu2[2048];
__device__ float g_v1[16384], g_v2[16384];
__device__ float g_lse1[16384], g_lse2[16384];
__device__ int   g_am1[16384], g_am2[16384];
__device__ double g_S[2];
__device__ double g_ce[2];
__device__ float g_avgp[2048];
__device__ int   g_hist[2048];
__device__ int   g_accc[2];
__device__ float g_misc[4];

__device__ __forceinline__ float* LB(int v){ return v ? g_L2 : g_L1; }
__device__ __forceinline__ float* UB(int v){ return v ? g_u2 : g_u1; }
__device__ __forceinline__ float* VBv(int v){ return v ? g_v2 : g_v1; }
__device__ __forceinline__ float* LUB(int v){ return v ? g_lu2 : g_lu1; }
__device__ __forceinline__ float* LSEB(int v){ return v ? g_lse2 : g_lse1; }
__device__ __forceinline__ int*   AMB(int v){ return v ? g_am2 : g_am1; }
__device__ __forceinline__ float* GBv(int v){ return v ? g_G2 : g_G1; }

__device__ __forceinline__ void bsplit(float x, __nv_bfloat16& h, __nv_bfloat16& l){
    h = __float2bfloat16(x);
    l = __float2bfloat16(x - __bfloat162float(h));
}

// ======================= zeroing =======================
__global__ void k_zero_main(){
    int i = blockIdx.x*256 + threadIdx.x;
    if (i < 2048){ g_avgp[i]=0.f; g_hist[i]=0; }
    if (i < 512){ g_csum[0][i]=0.f; g_csum[1][i]=0.f; }
    if (i == 0){
        g_S[0]=0.0; g_S[1]=0.0; g_ce[0]=0.0; g_ce[1]=0.0;
        g_accc[0]=0; g_accc[1]=0;
        g_misc[0]=0.f; g_misc[1]=0.f; g_misc[2]=0.f; g_misc[3]=0.f;
    }
}
__global__ void k_zero_G(){
    int i = blockIdx.x*256 + threadIdx.x;
    if (i < 262144){ g_G1[i]=0.f; g_G2[i]=0.f; }
}
__global__ void k_zero_t(){
    int i = blockIdx.x*256 + threadIdx.x;
    if (i < 2048) g_t[i]=0.f;
}

// ======================= column sums =======================
__global__ void k_colstats(const float* __restrict__ z, int view){
    int d = threadIdx.x;
    size_t r0 = (size_t)blockIdx.x * 128;
    float s=0.f;
    #pragma unroll 4
    for (int r=0;r<128;r++){ s += z[(r0+r)*512 + d]; }
    atomicAdd(&g_csum[view][d], s);
}

// ======================= row l2 normalize -> bf16 hi/lo =======================
__global__ void k_rownorm(const float* __restrict__ z, int view){
    int row = blockIdx.x, t = threadIdx.x;
    __shared__ float sm[128];
    float4 v = reinterpret_cast<const float4*>(z)[(size_t)row*128 + t];
    float s = v.x*v.x + v.y*v.y + v.z*v.z + v.w*v.w;
    sm[t]=s; __syncthreads();
    for (int o=64;o;o>>=1){ if (t<o) sm[t]+=sm[t+o]; __syncthreads(); }
    float inv = 1.f / fmaxf(sqrtf(sm[0]), 1e-12f);
    __nv_bfloat16* H = view ? g_znh2 : g_znh1;
    __nv_bfloat16* L = view ? g_znl2 : g_znl1;
    size_t o = (size_t)row*512 + t*4;
    __nv_bfloat16 h0,h1,h2,h3,l0,l1,l2,l3;
    bsplit(v.x*inv,h0,l0); bsplit(v.y*inv,h1,l1);
    bsplit(v.z*inv,h2,l2); bsplit(v.w*inv,h3,l3);
    __nv_bfloat162* Hp = reinterpret_cast<__nv_bfloat162*>(H + o);
    __nv_bfloat162* Lp = reinterpret_cast<__nv_bfloat162*>(L + o);
    Hp[0] = __nv_bfloat162(h0,h1); Hp[1] = __nv_bfloat162(h2,h3);
    Lp[0] = __nv_bfloat162(l0,l1); Lp[1] = __nv_bfloat162(l2,l3);
}

// ======================= transpose z -> zT bf16 hi/lo =======================
__global__ void k_ztrans(const float* __restrict__ z, int view){
    __shared__ float t[32][33];
    __nv_bfloat16* TH = view ? g_zth2 : g_zth1;
    __nv_bfloat16* TL = view ? g_ztl2 : g_ztl1;
    int x0 = blockIdx.x*32, y0 = blockIdx.y*32;
    int tx = threadIdx.x, ty = threadIdx.y;
    #pragma unroll
    for (int i=0;i<32;i+=8)
        t[ty+i][tx] = z[(size_t)(y0+ty+i)*512 + x0 + tx];
    __syncthreads();
    #pragma unroll
    for (int i=0;i<32;i+=8){
        float v = t[tx][ty+i];
        __nv_bfloat16 h,l; bsplit(v,h,l);
        size_t o = (size_t)(x0+ty+i)*16384 + y0 + tx;
        TH[o]=h; TL[o]=l;
    }
}

// ======================= W -> bf16 hi/lo =======================
__global__ void k_wsplit(const float* __restrict__ W){
    int i = blockIdx.x*512 + threadIdx.x;
    bsplit(W[i], g_wh[i], g_wl[i]);
}

// ======================= HMMA GEMM (BM=128,BN=128,BK=32, 3-term bf16 split) =======================
// smem: per stage A 128 rows x 80B + B 128 rows x 80B (32 bf16 data + 8 pad)
// padded rows make ldmatrix conflict-free (r*80 mod 128 distinct for r in 0..7).
#define SMEM_STAGE 20480
#define ROWB 80

__global__ void __launch_bounds__(256,2) k_mma_gemm(int which){
    const __nv_bfloat16 *Ah,*Al,*Bh,*Bl;
    float* C; size_t ldk; int ldc, atomic_epi;
    if (which == 0){ Ah=g_znh1; Al=g_znl1; Bh=g_wh; Bl=g_wl; C=g_L1; ldk=512; ldc=2048; atomic_epi=0; }
    else if (which == 1){ Ah=g_znh2; Al=g_znl2; Bh=g_wh; Bl=g_wl; C=g_L2; ldk=512; ldc=2048; atomic_epi=0; }
    else if (which == 2){ Ah=g_zth1; Al=g_ztl1; Bh=g_zth1; Bl=g_ztl1; C=g_G1; ldk=16384; ldc=512; atomic_epi=1; }
    else { Ah=g_zth2; Al=g_ztl2; Bh=g_zth2; Bl=g_ztl2; C=g_G2; ldk=16384; ldc=512; atomic_epi=1; }

    __shared__ __align__(128) char smem[2*SMEM_STAGE];
    uint32_t sb = smem_to_u32(smem);

    int tid = threadIdx.x;
    int wid = tid >> 5, lane = tid & 31;
    int wm = wid >> 2, wn = wid & 3;        // warp tile: rows wm*64, cols wn*32
    int g = lane >> 2, tig = lane & 3;

    int bm = blockIdx.y*128, bn = blockIdx.x*128;
    size_t kz = (size_t)blockIdx.z * 512;   // 512-K chunk per CTA (z=1 chunk for logits)

    const __nv_bfloat16* Aterm[3] = {Ah, Ah, Al};
    const __nv_bfloat16* Bterm[3] = {Bh, Bl, Bh};

    float acc[4][4][4];
    #pragma unroll
    for (int mf=0;mf<4;mf++)
        #pragma unroll
        for (int nf=0;nf<4;nf++)
            #pragma unroll
            for (int q=0;q<4;q++) acc[mf][nf][q]=0.f;

    // per-thread load coords: 512 chunks of 16B per operand, 2 per thread
    int r0c = tid >> 2, c0c = tid & 3;             // chunk 0: row, 16B-chunk
    int r1c = (tid+256) >> 2, c1c = tid & 3;       // chunk 1

    auto load_stage = [&](int it, int s){
        int term = it >> 4; int kb = it & 15;
        const __nv_bfloat16* Ap = Aterm[term] + (size_t)bm*ldk + kz + kb*32;
        const __nv_bfloat16* Bp = Bterm[term] + (size_t)bn*ldk + kz + kb*32;
        uint32_t baseA = sb + s*SMEM_STAGE;
        uint32_t baseB = baseA + 10240;
        CP_ASYNC16(baseA + r0c*ROWB + c0c*16, Ap + (size_t)r0c*ldk + c0c*8);
        CP_ASYNC16(baseA + r1c*ROWB + c1c*16, Ap + (size_t)r1c*ldk + c1c*8);
        CP_ASYNC16(baseB + r0c*ROWB + c0c*16, Bp + (size_t)r0c*ldk + c0c*8);
        CP_ASYNC16(baseB + r1c*ROWB + c1c*16, Bp + (size_t)r1c*ldk + c1c*8);
        CP_COMMIT();
    };

    load_stage(0,0);
    load_stage(1,1);

    // ldmatrix lane addressing (byte offsets within stage)
    // A: row = wm*64 + mf*16 + (lane&7) + ((lane>>3)&1)*8 ; kcol byte = ks*32 + (lane>>4)*16
    int arow_base = wm*64 + (lane&7) + ((lane>>3)&1)*8;
    int akoff     = (lane>>4)*16;
    // B: row = wn*32 + nh*16 + (lane&7) + (lane>>4)*8 ; kcol byte = ks*32 + ((lane>>3)&1)*16
    int brow_base = wn*32 + (lane&7) + (lane>>4)*8;
    int bkoff     = ((lane>>3)&1)*16;

    for (int it=0; it<48; it++){
        int s = it & 1;
        if (it == 47) { CP_WAIT(0); } else { CP_WAIT(1); }
        __syncthreads();
        uint32_t baseA = sb + s*SMEM_STAGE;
        uint32_t baseB = baseA + 10240;
        #pragma unroll
        for (int ks=0; ks<2; ks++){
            uint32_t a[4][4], b[4][2];
            #pragma unroll
            for (int mf=0; mf<4; mf++){
                uint32_t ad = baseA + (arow_base + mf*16)*ROWB + ks*32 + akoff;
                LDMATRIX_X4(a[mf][0],a[mf][1],a[mf][2],a[mf][3], ad);
            }
            #pragma unroll
            for (int nh=0; nh<2; nh++){
                uint32_t bd = baseB + (brow_base + nh*16)*ROWB + ks*32 + bkoff;
                LDMATRIX_X4(b[nh*2][0],b[nh*2][1],b[nh*2+1][0],b[nh*2+1][1], bd);
            }
            #pragma unroll
            for (int mf=0; mf<4; mf++)
                #pragma unroll
                for (int nf=0; nf<4; nf++)
                    mma16816(acc[mf][nf], a[mf], b[nf]);
        }
        __syncthreads();
        if (it+2 < 48) load_stage(it+2, s);
    }

    // epilogue
    #pragma unroll
    for (int mf=0; mf<4; mf++){
        int r0 = bm + wm*64 + mf*16 + g;
        #pragma unroll
        for (int nf=0; nf<4; nf++){
            int cc = bn + wn*32 + nf*8 + tig*2;
            if (!atomic_epi){
                float2* p0 = reinterpret_cast<float2*>(C + (size_t)r0*ldc + cc);
                float2* p1 = reinterpret_cast<float2*>(C + (size_t)(r0+8)*ldc + cc);
                *p0 = make_float2(acc[mf][nf][0], acc[mf][nf][1]);
                *p1 = make_float2(acc[mf][nf][2], acc[mf][nf][3]);
            } else {
                atomicAdd(C + (size_t)r0*ldc + cc,       acc[mf][nf][0]);
                atomicAdd(C + (size_t)r0*ldc + cc + 1,   acc[mf][nf][1]);
                atomicAdd(C + (size_t)(r0+8)*ldc + cc,   acc[mf][nf][2]);
                atomicAdd(C + (size_t)(r0+8)*ldc + cc+1, acc[mf][nf][3]);
            }
        }
    }
}

// ======================= covariance / variance losses =======================
__global__ void k_covfin(int view){
    int i = blockIdx.x, j = threadIdx.x;
    __shared__ float sm[512];
    const float* G = GBv(view);
    float mi = g_csum[view][i] * (1.f/16384.f);
    float mj = g_csum[view][j] * (1.f/16384.f);
    float Cij = (G[(size_t)i*512 + j] - 16384.f*mi*mj) * (1.f/16383.f);
    float c2 = (i==j) ? 0.f : Cij*Cij;
    sm[j]=c2; __syncthreads();
    for (int o=256;o;o>>=1){ if (j<o) sm[j]+=sm[j+o]; __syncthreads(); }
    if (j==0) atomicAdd(&g_misc[view*2+1], sm[0]*(1.f/512.f));
    if (j==i){
        float term = fmaxf(0.f, 0.2f - sqrtf(Cij + 1e-8f));
        atomicAdd(&g_misc[view*2+0], term*(1.f/512.f));
    }
}

// ======================= per-row max/argmax + logsumexp =======================
__global__ void k_rowstats(int view){
    int b = blockIdx.x, tid = threadIdx.x;
    const float* L = LB(view);
    const float4* Lr = reinterpret_cast<const float4*>(L + (size_t)b*2048);
    float4 x0 = Lr[tid*2], x1 = Lr[tid*2+1];
    float v[8] = {x0.x,x0.y,x0.z,x0.w,x1.x,x1.y,x1.z,x1.w};
    float m = v[0]; int mi = tid*8;
    #pragma unroll
    for (int j=1;j<8;j++) if (v[j]>m){ m=v[j]; mi=tid*8+j; }
    __shared__ float sm[256]; __shared__ int si[256];
    sm[tid]=m; si[tid]=mi; __syncthreads();
    for (int o=128;o;o>>=1){
        if (tid<o){
            if (sm[tid+o]>sm[tid] || (sm[tid+o]==sm[tid] && si[tid+o]<si[tid])){
                sm[tid]=sm[tid+o]; si[tid]=si[tid+o];
            }
        }
        __syncthreads();
    }
    float M = sm[0]; int gidx = si[0];
    __syncthreads();
    float se=0.f;
    #pragma unroll
    for (int j=0;j<8;j++) se += __expf((v[j]-M)*10.f);
    sm[tid]=se; __syncthreads();
    for (int o=128;o;o>>=1){ if (tid<o) sm[tid]+=sm[tid+o]; __syncthreads(); }
    if (tid==0){ LSEB(view)[b] = M*10.f + logf(sm[0]); AMB(view)[b] = gidx; }
}

// ======================= sinkhorn column pass =======================
__global__ void k_colpass(int view, int useV, int withS){
    __shared__ float sm[256];
    int k = blockIdx.x*256 + threadIdx.x;
    size_t b0 = (size_t)blockIdx.y * 128;
    const float* L = LB(view);
    float s = 0.f;
    if (useV){
        const float* v = VBv(view);
        #pragma unroll 8
        for (int r=0;r<128;r++)
            s += __expf(20.f * L[(b0+r)*2048 + k]) * v[b0+r];
    } else {
        #pragma unroll 8
        for (int r=0;r<128;r++)
            s += __expf(20.f * L[(b0+r)*2048 + k]);
    }
    atomicAdd(&g_t[k], s);
    if (withS){
        sm[threadIdx.x]=s; __syncthreads();
        for (int o=128;o;o>>=1){ if (threadIdx.x<o) sm[threadIdx.x]+=sm[threadIdx.x+o]; __syncthreads(); }
        if (threadIdx.x==0) atomicAdd(&g_S[view], (double)sm[0]);
    }
}
__global__ void k_uinit(int view){
    int k = blockIdx.x*256 + threadIdx.x;
    UB(view)[k] = (float)(g_S[view]) / (2048.f * g_t[k]);
}
__global__ void k_ufromt(int view){
    int k = blockIdx.x*256 + threadIdx.x;
    UB(view)[k] = 1.f / (2048.f * g_t[k]);
}
__global__ void k_logu(int view){
    int k = blockIdx.x*256 + threadIdx.x;
    LUB(view)[k] = logf(UB(view)[k]);
}
__global__ void k_rowpass(int view){
    int b = blockIdx.x, tid = threadIdx.x;
    const float* L = LB(view);
    const float4* Lr = reinterpret_cast<const float4*>(L + (size_t)b*2048);
    const float4* Ur = reinterpret_cast<const float4*>(UB(view));
    float s = 0.f;
    #pragma unroll
    for (int j=0;j<2;j++){
        float4 x = Lr[tid*2+j]; float4 uu = Ur[tid*2+j];
        s += __expf(20.f*x.x)*uu.x + __expf(20.f*x.y)*uu.y
           + __expf(20.f*x.z)*uu.z + __expf(20.f*x.w)*uu.w;
    }
    __shared__ float sm[256];
    sm[tid]=s; __syncthreads();
    for (int o=128;o;o>>=1){ if (tid<o) sm[tid]+=sm[tid+o]; __syncthreads(); }
    if (tid==0) VBv(view)[b] = 1.f / (16384.f * sm[0]);
}

// ======================= fused final pass =======================
__global__ void k_final(){
    __shared__ float s_avgp[2048];
    __shared__ float smf[256]; __shared__ int smi[256];
    __shared__ double smd[256];
    int tid = threadIdx.x;
    int kbase = tid*8;
    float U1[8],U2[8],LU1[8],LU2[8];
    #pragma unroll
    for (int j=0;j<8;j++){
        U1[j]=g_u1[kbase+j]; U2[j]=g_u2[kbase+j];
        LU1[j]=g_lu1[kbase+j]; LU2[j]=g_lu2[kbase+j];
        s_avgp[kbase+j]=0.f;
    }
    __syncthreads();
    double tce1=0.0, tce2=0.0;
    int tacc1=0, tacc2=0;
    int b0 = blockIdx.x*16;
    for (int r=0;r<16;r++){
        int b = b0 + r;
        const float4* L1r = reinterpret_cast<const float4*>(g_L1 + (size_t)b*2048);
        const float4* L2r = reinterpret_cast<const float4*>(g_L2 + (size_t)b*2048);
        float4 a0=L1r[tid*2], a1=L1r[tid*2+1];
        float4 c0=L2r[tid*2], c1=L2r[tid*2+1];
        float A[8]={a0.x,a0.y,a0.z,a0.w,a1.x,a1.y,a1.z,a1.w};
        float C[8]={c0.x,c0.y,c0.z,c0.w,c1.x,c1.y,c1.z,c1.w};
        float cv1 = 16384.f*g_v1[b], cv2 = 16384.f*g_v2[b];
        float ls1 = g_lse1[b], ls2 = g_lse2[b];
        float sc1=0.f, sc2=0.f;
        float m1=-1e30f, m2=-1e30f; int i1=0, i2=0;
        #pragma unroll
        for (int j=0;j<8;j++){
            float a=A[j], c=C[j];
            float lp1 = 10.f*a - ls1;
            float lp2 = 10.f*c - ls2;
            float t1 = cv1*U1[j]*__expf(20.f*a);
            float t2 = cv2*U2[j]*__expf(20.f*c);
            sc1 += t1*lp2;
            sc2 += t2*lp1;
            s_avgp[kbase+j] += __expf(lp1) + __expf(lp2);
            float g1 = 20.f*a + LU1[j];
            if (g1>m1){ m1=g1; i1=kbase+j; }
            float g2 = 20.f*c + LU2[j];
            if (g2>m2){ m2=g2; i2=kbase+j; }
        }
        tce1 += (double)sc1; tce2 += (double)sc2;
        smf[tid]=m2; smi[tid]=i2; __syncthreads();
        for (int o=128;o;o>>=1){
            if (tid<o && (smf[tid+o]>smf[tid] || (smf[tid+o]==smf[tid] && smi[tid+o]<smi[tid]))){
                smf[tid]=smf[tid+o]; smi[tid]=smi[tid+o];
            }
            __syncthreads();
        }
        if (tid==0 && smi[0]==g_am1[b]) tacc1++;
        __syncthreads();
        smf[tid]=m1; smi[tid]=i1; __syncthreads();
        for (int o=128;o;o>>=1){
            if (tid<o && (smf[tid+o]>smf[tid] || (smf[tid+o]==smf[tid] && smi[tid+o]<smi[tid]))){
                smf[tid]=smf[tid+o]; smi[tid]=smi[tid+o];
            }
            __syncthreads();
        }
        if (tid==0 && smi[0]==g_am2[b]) tacc2++;
        __syncthreads();
    }
    smd[tid]=tce1; __syncthreads();
    for (int o=128;o;o>>=1){ if (tid<o) smd[tid]+=smd[tid+o]; __syncthreads(); }
    if (tid==0) atomicAdd(&g_ce[0], smd[0]);
    __syncthreads();
    smd[tid]=tce2; __syncthreads();
    for (int o=128;o;o>>=1){ if (tid<o) smd[tid]+=smd[tid+o]; __syncthreads(); }
    if (tid==0) atomicAdd(&g_ce[1], smd[0]);
    __syncthreads();
    #pragma unroll
    for (int j=0;j<8;j++) atomicAdd(&g_avgp[kbase+j], s_avgp[kbase+j]);
    if (tid==0){ atomicAdd(&g_accc[0], tacc1); atomicAdd(&g_accc[1], tacc2); }
}

__global__ void k_hist(){
    int i = blockIdx.x*256 + threadIdx.x;
    if (i < 16384){
        atomicAdd(&g_hist[g_am1[i]], 1);
        atomicAdd(&g_hist[g_am2[i]], 1);
    }
}

__global__ void k_finalize(float* __restrict__ out){
    __shared__ double smd[256];
    int tid = threadIdx.x;
    double sh=0.0, sp=0.0;
    for (int j=0;j<8;j++){
        int k = tid*8 + j;
        double hp = (double)g_hist[k] / 32768.0;
        sh += hp * log(hp + 1e-7);
        double pp = (double)g_avgp[k] / 32768.0;
        sp += pp * log(pp + 1e-7);
    }
    smd[tid]=sh; __syncthreads();
    for (int o=128;o;o>>=1){ if (tid<o) smd[tid]+=smd[tid+o]; __syncthreads(); }
    double H = smd[0]; __syncthreads();
    smd[tid]=sp; __syncthreads();
    for (int o=128;o;o>>=1){ if (tid<o) smd[tid]+=smd[tid+o]; __syncthreads(); }
    double P = smd[0];
    if (tid==0){
        double ce = -0.5 * (g_ce[0]/16384.0 + g_ce[1]/16384.0);
        float lvar = g_misc[0] + g_misc[2];
        float lcov = g_misc[1] + g_misc[3];
        double loss = 15.0*ce + (double)lvar + (double)lcov;
        out[0] = (float)loss;
        out[1] = (float)ce;
        out[2] = lvar;
        out[3] = lcov;
        out[4] = (float)exp(-H);
        out[5] = (float)exp(-P);
        out[6] = 0.5f * ((float)g_accc[0] + (float)g_accc[1]) / 16384.f;
    }
}

// ======================= launch =======================
extern "C" void kernel_launch(void* const* d_in, const int* in_sizes, int n_in,
                              void* d_out, int out_size){
    const float* z1 = (const float*)d_in[0];
    const float* z2 = (const float*)d_in[1];
    const float* W  = (const float*)d_in[2];
    float* out = (float*)d_out;

    k_zero_main<<<8,256>>>();
    k_zero_G<<<1024,256>>>();
    k_wsplit<<<2048,512>>>(W);

    for (int view=0; view<2; view++){
        const float* z = view ? z2 : z1;
        k_colstats<<<128,512>>>(z, view);
        k_rownorm<<<Bn,128>>>(z, view);
        k_ztrans<<<dim3(16,512),dim3(32,8)>>>(z, view);
    }

    // logits GEMMs: [16384 x 2048] = zn @ W^T  (K=512, 3-term split)
    k_mma_gemm<<<dim3(16,128,1),256>>>(0);
    k_mma_gemm<<<dim3(16,128,1),256>>>(1);
    // covariance GEMMs: [512 x 512] = z^T z, split-K=32 chunks of 512
    k_mma_gemm<<<dim3(4,4,32),256>>>(2);
    k_mma_gemm<<<dim3(4,4,32),256>>>(3);

    k_covfin<<<512,512>>>(0);
    k_covfin<<<512,512>>>(1);

    for (int view=0; view<2; view++){
        k_rowstats<<<Bn,256>>>(view);
    }

    for (int view=0; view<2; view++){
        k_zero_t<<<8,256>>>();
        k_colpass<<<dim3(8,128),256>>>(view, 0, 1);
        k_uinit<<<8,256>>>(view);
        k_rowpass<<<Bn,256>>>(view);

        k_zero_t<<<8,256>>>();
        k_colpass<<<dim3(8,128),256>>>(view, 1, 0);
        k_ufromt<<<8,256>>>(view);
        k_rowpass<<<Bn,256>>>(view);

        k_zero_t<<<8,256>>>();
        k_colpass<<<dim3(8,128),256>>>(view, 1, 0);
        k_ufromt<<<8,256>>>(view);
        k_logu<<<8,256>>>(view);
        k_rowpass<<<Bn,256>>>(view);
    }

    k_final<<<1024,256>>>();
    k_hist<<<64,256>>>();
    k_finalize<<<1,256>>>(out);
}